// round 1
// baseline (speedup 1.0000x reference)
#include <cuda_runtime.h>
#include <math.h>

#define BB 2
#define CC 64
#define NPTS 4096
#define MM 256
#define NS 32
#define R2 0.04f

// -------- scratch (device globals; no allocation allowed) --------
__device__ int    g_idx[BB*NPTS*NS];
__device__ int    g_cnt[BB*NPTS];
__device__ float  g_hraw[BB*MM*NPTS];    // (B, M, N)
__device__ float  g_feats[BB*NPTS*MM];   // (B, N, M)  gelu(gn1(h))
__device__ float  g_h2[BB*NPTS*MM];      // (B, N, M)
__device__ float  g_oraw[BB*CC*NPTS];    // (B, C, N)
__device__ double g_s1[8], g_ss1[8], g_s2[8], g_ss2[8], g_s3[8], g_ss3[8];

__device__ __forceinline__ float gelu_f(float v) {
    return 0.5f * v * (1.0f + erff(v * 0.70710678118654752f));
}

// -------- K0: zero counts + stats --------
__global__ void k_zero() {
    int i = blockIdx.x * 256 + threadIdx.x;
    if (i < BB*NPTS) g_cnt[i] = 0;
    if (i < 8) {
        g_s1[i]=0.0; g_ss1[i]=0.0;
        g_s2[i]=0.0; g_ss2[i]=0.0;
        g_s3[i]=0.0; g_ss3[i]=0.0;
    }
}

// -------- K1: ball query (one warp per query point) + counts --------
__global__ void k_ball(const float* __restrict__ pos) {
    extern __shared__ float sm[];
    float* sx = sm;
    float* sy = sm + NPTS;
    float* sz = sm + 2*NPTS;
    int*   widx = (int*)(sm + 3*NPTS);   // 8 warps * 32 entries

    int tid = threadIdx.x;
    int b = blockIdx.x / (NPTS/8);
    int nbase = (blockIdx.x % (NPTS/8)) * 8;
    const float* pb = pos + b * 3 * NPTS;
    for (int i = tid; i < NPTS; i += 256) {
        sx[i] = pb[i];
        sy[i] = pb[NPTS + i];
        sz[i] = pb[2*NPTS + i];
    }
    __syncthreads();

    int warp = tid >> 5, lane = tid & 31;
    int n = nbase + warp;
    float xn = sx[n], yn = sy[n], zn = sz[n];
    float sqn = xn*xn + yn*yn + zn*zn;
    int cnt = 0, firstm = -1;
    int* wl = widx + warp * NS;

    for (int base = 0; base < NPTS && cnt < NS; base += 32) {
        int mq = base + lane;
        float xm = sx[mq], ym = sy[mq], zm = sz[mq];
        float sqm = xm*xm + ym*ym + zm*zm;
        float dot = xn*xm + yn*ym + zn*zm;
        float d = sqn + sqm - 2.0f * dot;
        bool q = !(d > R2);
        unsigned mask = __ballot_sync(0xffffffffu, q);
        if (mask) {
            if (firstm < 0) firstm = base + __ffs(mask) - 1;
            int nq = __popc(mask);
            int slots = NS - cnt;
            if (q) {
                int rank = __popc(mask & ((1u << lane) - 1u));
                if (rank < slots) wl[cnt + rank] = mq;
            }
            cnt += (nq < slots) ? nq : slots;
        }
    }
    __syncwarp();
    if (lane >= cnt) wl[lane] = firstm;   // pad with first qualifying index
    __syncwarp();
    int j = wl[lane];
    g_idx[(b*NPTS + n)*NS + lane] = j;
    atomicAdd(&g_cnt[b*NPTS + j], 1);
}

// -------- K2: h_raw = w1 @ x + b1, fused GN1 stats --------
// grid (N/64, M/64, B), block 256, thread 4x4 micro-tile
__global__ void k_gemm1(const float* __restrict__ x, const float* __restrict__ w1,
                        const float* __restrict__ b1) {
    __shared__ float sW[64][65];
    __shared__ float sX[64][64];
    __shared__ float red1[256], red2[256];
    int b = blockIdx.z, m0 = blockIdx.y * 64, n0 = blockIdx.x * 64;
    int tid = threadIdx.x;
    for (int e = tid; e < 4096; e += 256) {
        int mr = e >> 6, cr = e & 63;
        sW[mr][cr] = w1[(m0 + mr)*CC + cr];
    }
    for (int e = tid; e < 4096; e += 256) {
        int cr = e >> 6, nr = e & 63;
        sX[cr][nr] = x[(b*CC + cr)*NPTS + n0 + nr];
    }
    __syncthreads();

    int tx = tid & 15, ty = tid >> 4;
    float acc[4][4] = {};
#pragma unroll 16
    for (int k = 0; k < 64; k++) {
        float a[4], h[4];
#pragma unroll
        for (int i = 0; i < 4; i++) a[i] = sW[ty*4 + i][k];
#pragma unroll
        for (int j = 0; j < 4; j++) h[j] = sX[k][tx*4 + j];
#pragma unroll
        for (int i = 0; i < 4; i++)
#pragma unroll
            for (int j = 0; j < 4; j++)
                acc[i][j] = fmaf(a[i], h[j], acc[i][j]);
    }

    float lsum = 0.f, lss = 0.f;
#pragma unroll
    for (int i = 0; i < 4; i++) {
        int mrow = m0 + ty*4 + i;
        float bb = b1[mrow];
        float v0 = acc[i][0] + bb, v1 = acc[i][1] + bb;
        float v2 = acc[i][2] + bb, v3 = acc[i][3] + bb;
        float4 o; o.x = v0; o.y = v1; o.z = v2; o.w = v3;
        *(float4*)&g_hraw[(b*MM + mrow)*NPTS + n0 + tx*4] = o;
        lsum += v0 + v1 + v2 + v3;
        lss  += v0*v0 + v1*v1 + v2*v2 + v3*v3;
    }
    red1[tid] = lsum; red2[tid] = lss;
    __syncthreads();
    for (int s = 128; s > 0; s >>= 1) {
        if (tid < s) { red1[tid] += red1[tid + s]; red2[tid] += red2[tid + s]; }
        __syncthreads();
    }
    if (tid == 0) {
        int bg = b*4 + blockIdx.y;   // m-tile of 64 == one group
        atomicAdd(&g_s1[bg],  (double)red1[0]);
        atomicAdd(&g_ss1[bg], (double)red2[0]);
    }
}

// -------- K3: apply GN1 + GELU, transpose to feats(B,N,M), fused count-weighted GN2 stats --------
// grid (N/32, M/32, B), block (32,8)
__global__ void k_gn1t(const float* __restrict__ g1, const float* __restrict__ be1,
                       const float* __restrict__ wd) {
    __shared__ float tile[32][33];
    __shared__ float red1[256], red2[256];
    int b = blockIdx.z, m0 = blockIdx.y * 32, n0 = blockIdx.x * 32;
    int tx = threadIdx.x, ty = threadIdx.y;
    int tid = ty * 32 + tx;
    int bg = b*4 + (m0 >> 6);

    double mean = g_s1[bg] * (1.0 / (64.0 * 4096.0));
    double var  = g_ss1[bg] * (1.0 / (64.0 * 4096.0)) - mean * mean;
    float rs = (float)rsqrt(var + 1e-5);
    float mn = (float)mean;
    float w = (float)g_cnt[b*NPTS + n0 + tx];

    float lsum = 0.f, lss = 0.f;
#pragma unroll
    for (int i = 0; i < 4; i++) {
        int m = m0 + ty + 8*i;
        float v = g_hraw[(b*MM + m)*NPTS + n0 + tx];
        v = (v - mn) * rs * g1[m] + be1[m];
        v = gelu_f(v);
        tile[ty + 8*i][tx] = v;
        float v2 = v * wd[m];
        lsum += w * v2;
        lss  += w * v2 * v2;
    }
    __syncthreads();
#pragma unroll
    for (int i = 0; i < 4; i++) {
        int r = ty + 8*i;
        g_feats[(b*NPTS + n0 + r)*MM + m0 + tx] = tile[tx][r];
    }

    red1[tid] = lsum; red2[tid] = lss;
    __syncthreads();
    for (int s = 128; s > 0; s >>= 1) {
        if (tid < s) { red1[tid] += red1[tid + s]; red2[tid] += red2[tid + s]; }
        __syncthreads();
    }
    if (tid == 0) {
        atomicAdd(&g_s2[bg],  (double)red1[0]);
        atomicAdd(&g_ss2[bg], (double)red2[0]);
    }
}

// -------- K5: gather max/min + GN2 + max-pool + GELU -> h2(B,N,M) --------
// grid B*N blocks, 256 threads (one per channel m)
__global__ void k_gather(const float* __restrict__ wd, const float* __restrict__ gd,
                         const float* __restrict__ bed) {
    __shared__ int sI[NS];
    int blk = blockIdx.x;
    int b = blk >> 12, n = blk & (NPTS - 1);
    int tid = threadIdx.x;
    if (tid < NS) sI[tid] = g_idx[(b*NPTS + n)*NS + tid];
    __syncthreads();

    int m = tid;
    int bg = b*4 + (m >> 6);
    double mean = g_s2[bg] * (1.0 / 8388608.0);   // 64 * 4096 * 32
    double var  = g_ss2[bg] * (1.0 / 8388608.0) - mean * mean;
    float rs = (float)rsqrt(var + 1e-5);

    const float* base = g_feats + (size_t)(b*NPTS) * MM + m;
    float vmax = -1e30f, vmin = 1e30f;
#pragma unroll
    for (int s = 0; s < NS; s++) {
        float v = base[(size_t)sI[s] * MM];
        vmax = fmaxf(vmax, v);
        vmin = fminf(vmin, v);
    }
    float A  = wd[m] * rs * gd[m];
    float Bc = bed[m] - (float)mean * rs * gd[m];
    float v = (A >= 0.f) ? vmax : vmin;     // max of affine = affine of max/min
    g_h2[(b*NPTS + n)*MM + m] = gelu_f(fmaf(A, v, Bc));
}

// -------- K6: out_raw = w2 @ h2 + b2, fused GN3 stats --------
// grid (N/64, B), block 256; sW2/sH in dynamic shared (pitch 257)
__global__ void k_gemm2(const float* __restrict__ w2, const float* __restrict__ b2) {
    extern __shared__ float sm[];
    float* sW2 = sm;              // 64 * 257
    float* sH  = sm + 64 * 257;   // 64 * 257
    __shared__ float sacc[4], sss[4];
    int b = blockIdx.y, n0 = blockIdx.x * 64;
    int tid = threadIdx.x;
    if (tid < 4) { sacc[tid] = 0.f; sss[tid] = 0.f; }
    for (int e = tid; e < 64*256; e += 256) {
        int cr = e >> 8, k = e & 255;
        sW2[cr*257 + k] = w2[e];
    }
    for (int e = tid; e < 64*256; e += 256) {
        int nl = e >> 8, k = e & 255;
        sH[nl*257 + k] = g_h2[(b*NPTS + n0 + nl)*MM + k];
    }
    __syncthreads();

    int tx = tid & 15, ty = tid >> 4;
    float acc[4][4] = {};
#pragma unroll 8
    for (int k = 0; k < 256; k++) {
        float a[4], h[4];
#pragma unroll
        for (int i = 0; i < 4; i++) a[i] = sW2[(ty*4 + i)*257 + k];
#pragma unroll
        for (int j = 0; j < 4; j++) h[j] = sH[(tx*4 + j)*257 + k];
#pragma unroll
        for (int i = 0; i < 4; i++)
#pragma unroll
            for (int j = 0; j < 4; j++)
                acc[i][j] = fmaf(a[i], h[j], acc[i][j]);
    }

    float lsum = 0.f, lss = 0.f;
#pragma unroll
    for (int i = 0; i < 4; i++) {
        int c = ty*4 + i;
        float bb = b2[c];
        float v0 = acc[i][0] + bb, v1 = acc[i][1] + bb;
        float v2 = acc[i][2] + bb, v3 = acc[i][3] + bb;
        float4 o; o.x = v0; o.y = v1; o.z = v2; o.w = v3;
        *(float4*)&g_oraw[(b*CC + c)*NPTS + n0 + tx*4] = o;
        lsum += v0 + v1 + v2 + v3;
        lss  += v0*v0 + v1*v1 + v2*v2 + v3*v3;
    }
    int g = ty >> 2;   // c group = c/16; thread's 4 c's share a group
    atomicAdd(&sacc[g], lsum);
    atomicAdd(&sss[g],  lss);
    __syncthreads();
    if (tid < 4) {
        atomicAdd(&g_s3[b*4 + tid],  (double)sacc[tid]);
        atomicAdd(&g_ss3[b*4 + tid], (double)sss[tid]);
    }
}

// -------- K7: GN3 + residual --------
__global__ void k_final(const float* __restrict__ x, const float* __restrict__ g2,
                        const float* __restrict__ be2, float* __restrict__ out) {
    int i = blockIdx.x * 256 + threadIdx.x;
    if (i >= BB*CC*NPTS) return;
    int b = i >> 18;             // / (64*4096)
    int c = (i >> 12) & 63;
    int bg = b*4 + (c >> 4);
    double mean = g_s3[bg] * (1.0 / 65536.0);   // 16 * 4096
    double var  = g_ss3[bg] * (1.0 / 65536.0) - mean * mean;
    float rs = (float)rsqrt(var + 1e-5);
    out[i] = (g_oraw[i] - (float)mean) * rs * g2[c] + be2[c] + x[i];
}

extern "C" void kernel_launch(void* const* d_in, const int* in_sizes, int n_in,
                              void* d_out, int out_size) {
    const float* x   = (const float*)d_in[0];
    const float* pos = (const float*)d_in[1];
    const float* w1  = (const float*)d_in[2];
    const float* b1  = (const float*)d_in[3];
    const float* g1  = (const float*)d_in[4];
    const float* be1 = (const float*)d_in[5];
    const float* wd  = (const float*)d_in[6];
    const float* gd  = (const float*)d_in[7];
    const float* bed = (const float*)d_in[8];
    const float* w2  = (const float*)d_in[9];
    const float* b2  = (const float*)d_in[10];
    const float* g2  = (const float*)d_in[11];
    const float* be2 = (const float*)d_in[12];
    float* out = (float*)d_out;

    cudaFuncSetAttribute(k_ball,  cudaFuncAttributeMaxDynamicSharedMemorySize, 50176);
    cudaFuncSetAttribute(k_gemm2, cudaFuncAttributeMaxDynamicSharedMemorySize, 131584);

    k_zero <<<32, 256>>>();
    k_ball <<<BB*NPTS/8, 256, 50176>>>(pos);
    k_gemm1<<<dim3(NPTS/64, MM/64, BB), 256>>>(x, w1, b1);
    k_gn1t <<<dim3(NPTS/32, MM/32, BB), dim3(32, 8)>>>(g1, be1, wd);
    k_gather<<<BB*NPTS, 256>>>(wd, gd, bed);
    k_gemm2<<<dim3(NPTS/64, BB), 256, 131584>>>(w2, b2);
    k_final<<<(BB*CC*NPTS)/256, 256>>>(x, g2, be2, out);
}